// round 1
// baseline (speedup 1.0000x reference)
#include <cuda_runtime.h>
#include <cuda_bf16.h>

// Scratch: precomputed input-side gate activations xg[t][40] = transform @ W_ih^T + b_ih + b_hh
#define N_MAX 2048
__device__ float g_xg[N_MAX * 40];

// ---------------------------------------------------------------------------
// Phase 1: per-row MLP  (x[t,0] -> 32 -> 16) ++ (x[t,1] -> 32 -> 16) -> xg[40]
// One thread per row; all weights staged in shared memory (broadcast reads).
// ---------------------------------------------------------------------------
__global__ void phase1_kernel(const float* __restrict__ x,
                              const float* __restrict__ W_mz1, const float* __restrict__ b_mz1,
                              const float* __restrict__ W_mz2, const float* __restrict__ b_mz2,
                              const float* __restrict__ W_in1, const float* __restrict__ b_in1,
                              const float* __restrict__ W_in2, const float* __restrict__ b_in2,
                              const float* __restrict__ W_ih,  const float* __restrict__ b_ih,
                              const float* __restrict__ b_hh,  int n)
{
    __shared__ float s_Wmz1[32], s_bmz1[32], s_Wmz2[16 * 32], s_bmz2[16];
    __shared__ float s_Win1[32], s_bin1[32], s_Win2[16 * 32], s_bin2[16];
    __shared__ float s_Wih[40 * 32], s_b[40];

    for (int i = threadIdx.x; i < 32; i += blockDim.x) {
        s_Wmz1[i] = W_mz1[i]; s_bmz1[i] = b_mz1[i];
        s_Win1[i] = W_in1[i]; s_bin1[i] = b_in1[i];
    }
    for (int i = threadIdx.x; i < 16 * 32; i += blockDim.x) {
        s_Wmz2[i] = W_mz2[i]; s_Win2[i] = W_in2[i];
    }
    for (int i = threadIdx.x; i < 16; i += blockDim.x) {
        s_bmz2[i] = b_mz2[i]; s_bin2[i] = b_in2[i];
    }
    for (int i = threadIdx.x; i < 40 * 32; i += blockDim.x) s_Wih[i] = W_ih[i];
    for (int i = threadIdx.x; i < 40; i += blockDim.x) s_b[i] = b_ih[i] + b_hh[i];
    __syncthreads();

    int t = blockIdx.x * blockDim.x + threadIdx.x;
    if (t >= n) return;

    float x0 = x[2 * t + 0];
    float x1 = x[2 * t + 1];

    float a[32];
    float tr[32];

    // mz branch
    #pragma unroll
    for (int i = 0; i < 32; i++)
        a[i] = fmaxf(fmaf(x0, s_Wmz1[i], s_bmz1[i]), 0.0f);
    #pragma unroll 4
    for (int o = 0; o < 16; o++) {
        float acc = s_bmz2[o];
        #pragma unroll
        for (int i = 0; i < 32; i++) acc = fmaf(a[i], s_Wmz2[o * 32 + i], acc);
        tr[o] = fmaxf(acc, 0.0f);
    }
    // intensity branch
    #pragma unroll
    for (int i = 0; i < 32; i++)
        a[i] = fmaxf(fmaf(x1, s_Win1[i], s_bin1[i]), 0.0f);
    #pragma unroll 4
    for (int o = 0; o < 16; o++) {
        float acc = s_bin2[o];
        #pragma unroll
        for (int i = 0; i < 32; i++) acc = fmaf(a[i], s_Win2[o * 32 + i], acc);
        tr[16 + o] = fmaxf(acc, 0.0f);
    }
    // input-side gate preactivations
    #pragma unroll 4
    for (int g = 0; g < 40; g++) {
        float acc = s_b[g];
        #pragma unroll
        for (int i = 0; i < 32; i++) acc = fmaf(tr[i], s_Wih[g * 32 + i], acc);
        g_xg[t * 40 + g] = acc;
    }
}

// ---------------------------------------------------------------------------
// Phase 2: sequential LSTM scan, single warp.
// Lane j (j<10) owns hidden unit j; keeps W_hh rows {j, 10+j, 20+j, 30+j}
// in registers. h broadcast via shfl. xg prefetched 2 steps ahead.
// ---------------------------------------------------------------------------
__device__ __forceinline__ float fsigmoid(float v) {
    // 1 / (1 + exp(-v)) via fast EX2 + fast reciprocal (few-ulp accuracy)
    return __fdividef(1.0f, 1.0f + __expf(-v));
}
__device__ __forceinline__ float ftanh(float v) {
    float e = __expf(-2.0f * v);
    return __fdividef(1.0f - e, 1.0f + e);
}

__global__ void phase2_kernel(const float* __restrict__ W_hh,
                              float* __restrict__ out, int n)
{
    const int j = threadIdx.x;         // 0..31, lanes 0..9 active
    const bool act = (j < 10);

    float wi[10], wf[10], wg[10], wo[10];
    #pragma unroll
    for (int k = 0; k < 10; k++) {
        wi[k] = act ? W_hh[(j      ) * 10 + k] : 0.0f;
        wf[k] = act ? W_hh[(10 + j ) * 10 + k] : 0.0f;
        wg[k] = act ? W_hh[(20 + j ) * 10 + k] : 0.0f;
        wo[k] = act ? W_hh[(30 + j ) * 10 + k] : 0.0f;
    }

    float h = 0.0f, c = 0.0f;

    // xg register prefetch pipeline, depth 2
    float ci, cf, cg, co;   // current step t
    float ni, nf, ng, no;   // step t+1
    ci = act ? g_xg[0 * 40 +  0 + j] : 0.0f;
    cf = act ? g_xg[0 * 40 + 10 + j] : 0.0f;
    cg = act ? g_xg[0 * 40 + 20 + j] : 0.0f;
    co = act ? g_xg[0 * 40 + 30 + j] : 0.0f;
    if (n > 1) {
        ni = act ? g_xg[1 * 40 +  0 + j] : 0.0f;
        nf = act ? g_xg[1 * 40 + 10 + j] : 0.0f;
        ng = act ? g_xg[1 * 40 + 20 + j] : 0.0f;
        no = act ? g_xg[1 * 40 + 30 + j] : 0.0f;
    } else {
        ni = nf = ng = no = 0.0f;
    }

    for (int t = 0; t < n; t++) {
        // issue prefetch for t+2 first (L2 latency hidden across ~2 steps)
        float pi = 0.0f, pf = 0.0f, pg = 0.0f, po = 0.0f;
        if (act && (t + 2 < n)) {
            const float* p = g_xg + (t + 2) * 40 + j;
            pi = p[0]; pf = p[10]; pg = p[20]; po = p[30];
        }

        float ai = ci, af = cf, ag = cg, ao = co;
        #pragma unroll
        for (int k = 0; k < 10; k++) {
            float hk = __shfl_sync(0xFFFFFFFFu, h, k);
            ai = fmaf(hk, wi[k], ai);
            af = fmaf(hk, wf[k], af);
            ag = fmaf(hk, wg[k], ag);
            ao = fmaf(hk, wo[k], ao);
        }

        float si = fsigmoid(ai);
        float sf = fsigmoid(af);
        float so = fsigmoid(ao);
        float tg = ftanh(ag);

        c = fmaf(sf, c, si * tg);
        h = so * ftanh(c);

        if (act) out[t * 10 + j] = h;

        // rotate prefetch pipeline
        ci = ni; cf = nf; cg = ng; co = no;
        ni = pi; nf = pf; ng = pg; no = po;
    }
}

// ---------------------------------------------------------------------------
// Launch
// ---------------------------------------------------------------------------
extern "C" void kernel_launch(void* const* d_in, const int* in_sizes, int n_in,
                              void* d_out, int out_size)
{
    const float* x     = (const float*)d_in[0];
    const float* W_mz1 = (const float*)d_in[1];
    const float* b_mz1 = (const float*)d_in[2];
    const float* W_mz2 = (const float*)d_in[3];
    const float* b_mz2 = (const float*)d_in[4];
    const float* W_in1 = (const float*)d_in[5];
    const float* b_in1 = (const float*)d_in[6];
    const float* W_in2 = (const float*)d_in[7];
    const float* b_in2 = (const float*)d_in[8];
    const float* W_ih  = (const float*)d_in[9];
    const float* W_hh  = (const float*)d_in[10];
    const float* b_ih  = (const float*)d_in[11];
    const float* b_hh  = (const float*)d_in[12];
    float* out = (float*)d_out;

    int n = in_sizes[0] / 2;            // N timesteps (x is [N,2])
    if (n > N_MAX) n = N_MAX;

    const int TPB = 128;
    int blocks = (n + TPB - 1) / TPB;
    phase1_kernel<<<blocks, TPB>>>(x, W_mz1, b_mz1, W_mz2, b_mz2,
                                   W_in1, b_in1, W_in2, b_in2,
                                   W_ih, b_ih, b_hh, n);
    phase2_kernel<<<1, 32>>>(W_hh, out, n);
}

// round 2
// speedup vs baseline: 1.4752x; 1.4752x over previous
#include <cuda_runtime.h>
#include <cuda_bf16.h>

// Scratch: precomputed input-side gate activations xg[t][40] = transform @ W_ih^T + b_ih + b_hh
// Layout per row: [i0..i9, f0..f9, g0..g9, o0..o9]
#define N_MAX 2048
__device__ float g_xg[N_MAX * 40];

// ---------------------------------------------------------------------------
// Phase 1: per-row MLP  (x[t,0] -> 32 -> 16) ++ (x[t,1] -> 32 -> 16) -> xg[40]
// ---------------------------------------------------------------------------
__global__ void phase1_kernel(const float* __restrict__ x,
                              const float* __restrict__ W_mz1, const float* __restrict__ b_mz1,
                              const float* __restrict__ W_mz2, const float* __restrict__ b_mz2,
                              const float* __restrict__ W_in1, const float* __restrict__ b_in1,
                              const float* __restrict__ W_in2, const float* __restrict__ b_in2,
                              const float* __restrict__ W_ih,  const float* __restrict__ b_ih,
                              const float* __restrict__ b_hh,  int n)
{
    __shared__ float s_Wmz1[32], s_bmz1[32], s_Wmz2[16 * 32], s_bmz2[16];
    __shared__ float s_Win1[32], s_bin1[32], s_Win2[16 * 32], s_bin2[16];
    __shared__ float s_Wih[40 * 32], s_b[40];

    for (int i = threadIdx.x; i < 32; i += blockDim.x) {
        s_Wmz1[i] = W_mz1[i]; s_bmz1[i] = b_mz1[i];
        s_Win1[i] = W_in1[i]; s_bin1[i] = b_in1[i];
    }
    for (int i = threadIdx.x; i < 16 * 32; i += blockDim.x) {
        s_Wmz2[i] = W_mz2[i]; s_Win2[i] = W_in2[i];
    }
    for (int i = threadIdx.x; i < 16; i += blockDim.x) {
        s_bmz2[i] = b_mz2[i]; s_bin2[i] = b_in2[i];
    }
    for (int i = threadIdx.x; i < 40 * 32; i += blockDim.x) s_Wih[i] = W_ih[i];
    for (int i = threadIdx.x; i < 40; i += blockDim.x) s_b[i] = b_ih[i] + b_hh[i];
    __syncthreads();

    int t = blockIdx.x * blockDim.x + threadIdx.x;
    if (t >= n) return;

    float x0 = x[2 * t + 0];
    float x1 = x[2 * t + 1];

    float a[32];
    float tr[32];

    #pragma unroll
    for (int i = 0; i < 32; i++)
        a[i] = fmaxf(fmaf(x0, s_Wmz1[i], s_bmz1[i]), 0.0f);
    #pragma unroll 4
    for (int o = 0; o < 16; o++) {
        float acc = s_bmz2[o];
        #pragma unroll
        for (int i = 0; i < 32; i++) acc = fmaf(a[i], s_Wmz2[o * 32 + i], acc);
        tr[o] = fmaxf(acc, 0.0f);
    }
    #pragma unroll
    for (int i = 0; i < 32; i++)
        a[i] = fmaxf(fmaf(x1, s_Win1[i], s_bin1[i]), 0.0f);
    #pragma unroll 4
    for (int o = 0; o < 16; o++) {
        float acc = s_bin2[o];
        #pragma unroll
        for (int i = 0; i < 32; i++) acc = fmaf(a[i], s_Win2[o * 32 + i], acc);
        tr[16 + o] = fmaxf(acc, 0.0f);
    }
    #pragma unroll 4
    for (int g = 0; g < 40; g++) {
        float acc = s_b[g];
        #pragma unroll
        for (int i = 0; i < 32; i++) acc = fmaf(tr[i], s_Wih[g * 32 + i], acc);
        g_xg[t * 40 + g] = acc;
    }
}

// ---------------------------------------------------------------------------
// Phase 2: single-warp LSTM scan, 2 gate rows per lane.
//   lane l (0..19): A-gate = row l of W_hh   (i-gates 0-9, f-gates 10-19)
//                   B-gate = row l+20        (g-gates 0-9, o-gates 10-19)
//   lanes 20..31 mirror lanes 0..11 (results discarded) - zero divergence.
// Activations: warp-wide EX2+RCP with per-lane constants (sigmoid vs tanh).
// ---------------------------------------------------------------------------
__device__ __forceinline__ float ex2a(float x) {
    float y; asm("ex2.approx.f32 %0, %1;" : "=f"(y) : "f"(x)); return y;
}
__device__ __forceinline__ float rcpa(float x) {
    float y; asm("rcp.approx.f32 %0, %1;" : "=f"(y) : "f"(x)); return y;
}

__global__ __launch_bounds__(32, 1)
void phase2_kernel(const float* __restrict__ W_hh,
                   float* __restrict__ out, int n)
{
    const int l = threadIdx.x;                  // 0..31
    const int lm = (l < 20) ? l : (l - 20);     // clamp for mirror lanes
    const bool lt10 = (l < 10);

    // Per-lane weights: 20 regs total
    float wa[10], wb[10];
    #pragma unroll
    for (int k = 0; k < 10; k++) {
        wa[k] = W_hh[lm * 10 + k];
        wb[k] = W_hh[(lm + 20) * 10 + k];
    }

    // Per-lane activation constants:
    //   A is always a sigmoid (i or f).
    //   B: lanes<10 -> tanh(g);  lanes>=10 -> sigmoid(o)
    //   tanh(x) = 1 - 2/(1 + 2^(x*2*log2e));  sig(x) = 1/(1 + 2^(-x*log2e))
    const float NLOG2E = -1.442695041f;
    const float TLOG2E =  2.885390082f;
    const float mB = lt10 ? TLOG2E : NLOG2E;
    const float cB = lt10 ? -2.0f : 1.0f;
    const float dB = lt10 ?  1.0f : 0.0f;

    // xg pointers: lane l reads offsets l (A) and 20+l (B) of each 40-row
    const float* px = g_xg + lm;

    // depth-2 prefetch pipeline (g_xg has 2048 rows >= n+2; overreads unused)
    float a0 = px[0],  b0 = px[20];
    float a1 = px[40], b1 = px[60];
    px += 80;

    float h = 0.0f, c = 0.0f;

    for (int t = 0; t < n; t++) {
        // prefetch t+2 (unconditional, no branch)
        float a2 = px[0], b2 = px[20];
        px += 40;

        // gate pre-activations: two interleaved 10-deep FMA chains
        float A = a0, B = b0;
        #pragma unroll
        for (int k = 0; k < 10; k++) {
            float hk = __shfl_sync(0xFFFFFFFFu, h, k);
            A = fmaf(hk, wa[k], A);
            B = fmaf(hk, wb[k], B);
        }

        // warp-wide activations (4 MUFU total for all 40 gates)
        float sA   = rcpa(1.0f + ex2a(A * NLOG2E));          // sigmoid(i/f)
        float resB = fmaf(cB, rcpa(1.0f + ex2a(B * mB)), dB); // tanh(g) / sig(o)

        // fetch partner results: sig(f_j) and sig(o_j) live on lane l+10
        float sF = __shfl_sync(0xFFFFFFFFu, sA,   l + 10);
        float sO = __shfl_sync(0xFFFFFFFFu, resB, l + 10);

        // cell + hidden update (meaningful on lanes 0..9)
        c = fmaf(sF, c, sA * resB);
        float tc = fmaf(-2.0f, rcpa(1.0f + ex2a(c * TLOG2E)), 1.0f);
        h = sO * tc;

        if (lt10) out[t * 10 + l] = h;   // predicated STG, no branch

        // rotate prefetch pipeline
        a0 = a1; b0 = b1;
        a1 = a2; b1 = b2;
    }
}

// ---------------------------------------------------------------------------
// Launch
// ---------------------------------------------------------------------------
extern "C" void kernel_launch(void* const* d_in, const int* in_sizes, int n_in,
                              void* d_out, int out_size)
{
    const float* x     = (const float*)d_in[0];
    const float* W_mz1 = (const float*)d_in[1];
    const float* b_mz1 = (const float*)d_in[2];
    const float* W_mz2 = (const float*)d_in[3];
    const float* b_mz2 = (const float*)d_in[4];
    const float* W_in1 = (const float*)d_in[5];
    const float* b_in1 = (const float*)d_in[6];
    const float* W_in2 = (const float*)d_in[7];
    const float* b_in2 = (const float*)d_in[8];
    const float* W_ih  = (const float*)d_in[9];
    const float* W_hh  = (const float*)d_in[10];
    const float* b_ih  = (const float*)d_in[11];
    const float* b_hh  = (const float*)d_in[12];
    float* out = (float*)d_out;

    int n = in_sizes[0] / 2;            // N timesteps (x is [N,2])
    if (n > N_MAX) n = N_MAX;

    const int TPB = 128;
    int blocks = (n + TPB - 1) / TPB;
    phase1_kernel<<<blocks, TPB>>>(x, W_mz1, b_mz1, W_mz2, b_mz2,
                                   W_in1, b_in1, W_in2, b_in2,
                                   W_ih, b_ih, b_hh, n);
    phase2_kernel<<<1, 32>>>(W_hh, out, n);
}

// round 3
// speedup vs baseline: 1.7918x; 1.2146x over previous
#include <cuda_runtime.h>
#include <cuda_bf16.h>

// Scratch: precomputed input-side gate activations xg[t][40] = transform @ W_ih^T + b_ih + b_hh
// Layout per row: [i0..i9, f0..f9, g0..g9, o0..o9]
#define N_MAX 2048
__device__ float g_xg[N_MAX * 40];

// ---------------------------------------------------------------------------
// Phase 1: per-row MLP  (x[t,0] -> 32 -> 16) ++ (x[t,1] -> 32 -> 16) -> xg[40]
// ---------------------------------------------------------------------------
__global__ void phase1_kernel(const float* __restrict__ x,
                              const float* __restrict__ W_mz1, const float* __restrict__ b_mz1,
                              const float* __restrict__ W_mz2, const float* __restrict__ b_mz2,
                              const float* __restrict__ W_in1, const float* __restrict__ b_in1,
                              const float* __restrict__ W_in2, const float* __restrict__ b_in2,
                              const float* __restrict__ W_ih,  const float* __restrict__ b_ih,
                              const float* __restrict__ b_hh,  int n)
{
    __shared__ float s_Wmz1[32], s_bmz1[32], s_Wmz2[16 * 32], s_bmz2[16];
    __shared__ float s_Win1[32], s_bin1[32], s_Win2[16 * 32], s_bin2[16];
    __shared__ float s_Wih[40 * 32], s_b[40];

    for (int i = threadIdx.x; i < 32; i += blockDim.x) {
        s_Wmz1[i] = W_mz1[i]; s_bmz1[i] = b_mz1[i];
        s_Win1[i] = W_in1[i]; s_bin1[i] = b_in1[i];
    }
    for (int i = threadIdx.x; i < 16 * 32; i += blockDim.x) {
        s_Wmz2[i] = W_mz2[i]; s_Win2[i] = W_in2[i];
    }
    for (int i = threadIdx.x; i < 16; i += blockDim.x) {
        s_bmz2[i] = b_mz2[i]; s_bin2[i] = b_in2[i];
    }
    for (int i = threadIdx.x; i < 40 * 32; i += blockDim.x) s_Wih[i] = W_ih[i];
    for (int i = threadIdx.x; i < 40; i += blockDim.x) s_b[i] = b_ih[i] + b_hh[i];
    __syncthreads();

    int t = blockIdx.x * blockDim.x + threadIdx.x;
    if (t >= n) return;

    float x0 = x[2 * t + 0];
    float x1 = x[2 * t + 1];

    float a[32];
    float tr[32];

    #pragma unroll
    for (int i = 0; i < 32; i++)
        a[i] = fmaxf(fmaf(x0, s_Wmz1[i], s_bmz1[i]), 0.0f);
    #pragma unroll 4
    for (int o = 0; o < 16; o++) {
        float acc = s_bmz2[o];
        #pragma unroll
        for (int i = 0; i < 32; i++) acc = fmaf(a[i], s_Wmz2[o * 32 + i], acc);
        tr[o] = fmaxf(acc, 0.0f);
    }
    #pragma unroll
    for (int i = 0; i < 32; i++)
        a[i] = fmaxf(fmaf(x1, s_Win1[i], s_bin1[i]), 0.0f);
    #pragma unroll 4
    for (int o = 0; o < 16; o++) {
        float acc = s_bin2[o];
        #pragma unroll
        for (int i = 0; i < 32; i++) acc = fmaf(a[i], s_Win2[o * 32 + i], acc);
        tr[16 + o] = fmaxf(acc, 0.0f);
    }
    #pragma unroll 4
    for (int g = 0; g < 40; g++) {
        float acc = s_b[g];
        #pragma unroll
        for (int i = 0; i < 32; i++) acc = fmaf(tr[i], s_Wih[g * 32 + i], acc);
        g_xg[t * 40 + g] = acc;
    }
}

// ---------------------------------------------------------------------------
// Phase 2: single-warp LSTM scan.
//   group 0 = lanes 0..9  : A = i-row(lm),    B = g-row(20+lm)
//   group 1 = lanes 16..25: A = f-row(10+lm), B = o-row(30+lm)
//   partner exchange via shfl_xor(16).  Other lanes mirror (uniform flow).
// HW tanh (MUFU.TANH) for all nonlinearities:
//   sigmoid(x) = fma(0.5, tanh(0.5x), 0.5);  tanh(x) direct.
// ---------------------------------------------------------------------------
__device__ __forceinline__ float htanh(float x) {
    float y; asm("tanh.approx.f32 %0, %1;" : "=f"(y) : "f"(x)); return y;
}

__global__ __launch_bounds__(32, 1)
void phase2_kernel(const float* __restrict__ W_hh,
                   float* __restrict__ out, int n)
{
    const int l = threadIdx.x;                  // 0..31
    int base = l & 15;                          // 0..15
    if (base >= 10) base -= 6;                  // mirror lanes 10-15 -> 4-9
    const int grp = (l >> 4) & 1;               // 0: i/g rows, 1: f/o rows
    const int lm  = base + grp * 10;            // 0..19

    // Per-lane weights: A-row = W_hh[lm], B-row = W_hh[lm+20]
    float wa[10], wb[10];
    #pragma unroll
    for (int k = 0; k < 10; k++) {
        wa[k] = W_hh[lm * 10 + k];
        wb[k] = W_hh[(lm + 20) * 10 + k];
    }

    // B activation: group0 -> tanh(g): m=1,  c=1,   d=0
    //               group1 -> sig(o):  m=0.5,c=0.5, d=0.5
    const float mB = grp ? 0.5f : 1.0f;
    const float cB = grp ? 0.5f : 1.0f;
    const float dB = grp ? 0.5f : 0.0f;

    // xg pointer: A at row offset lm, B at row offset lm+20
    const float* px = g_xg + lm;

    // depth-2 prefetch pipeline (g_xg has 2048 rows >= n+2; overreads unused)
    float a0 = px[0],  b0 = px[20];
    float a1 = px[40], b1 = px[60];
    px += 80;

    float h = 0.0f, c = 0.0f;

    #pragma unroll 2
    for (int t = 0; t < n; t++) {
        // prefetch t+2 (unconditional)
        float a2 = px[0], b2 = px[20];
        px += 40;

        // gate pre-activations: 4 interleaved 5-deep FMA chains
        float A0 = a0, B0 = b0, A1 = 0.0f, B1 = 0.0f;
        #pragma unroll
        for (int k = 0; k < 5; k++) {
            float hk0 = __shfl_sync(0xFFFFFFFFu, h, k);
            float hk1 = __shfl_sync(0xFFFFFFFFu, h, k + 5);
            A0 = fmaf(hk0, wa[k],     A0);
            A1 = fmaf(hk1, wa[k + 5], A1);
            B0 = fmaf(hk0, wb[k],     B0);
            B1 = fmaf(hk1, wb[k + 5], B1);
        }
        float A = A0 + A1;
        float B = B0 + B1;

        // activations via HW tanh
        float sA   = fmaf(0.5f, htanh(0.5f * A), 0.5f);   // sigmoid(i or f)
        float resB = fmaf(cB,   htanh(mB * B),   dB);     // tanh(g) / sig(o)

        // partner exchange: group0 lane gets sig(f) and sig(o)
        float sF = __shfl_xor_sync(0xFFFFFFFFu, sA,   16);
        float sO = __shfl_xor_sync(0xFFFFFFFFu, resB, 16);

        // cell + hidden update (valid on lanes 0..9)
        c = fmaf(sF, c, sA * resB);
        h = sO * htanh(c);

        if (l < 10) out[t * 10 + l] = h;   // predicated STG

        // rotate prefetch pipeline
        a0 = a1; b0 = b1;
        a1 = a2; b1 = b2;
    }
}

// ---------------------------------------------------------------------------
// Launch
// ---------------------------------------------------------------------------
extern "C" void kernel_launch(void* const* d_in, const int* in_sizes, int n_in,
                              void* d_out, int out_size)
{
    const float* x     = (const float*)d_in[0];
    const float* W_mz1 = (const float*)d_in[1];
    const float* b_mz1 = (const float*)d_in[2];
    const float* W_mz2 = (const float*)d_in[3];
    const float* b_mz2 = (const float*)d_in[4];
    const float* W_in1 = (const float*)d_in[5];
    const float* b_in1 = (const float*)d_in[6];
    const float* W_in2 = (const float*)d_in[7];
    const float* b_in2 = (const float*)d_in[8];
    const float* W_ih  = (const float*)d_in[9];
    const float* W_hh  = (const float*)d_in[10];
    const float* b_ih  = (const float*)d_in[11];
    const float* b_hh  = (const float*)d_in[12];
    float* out = (float*)d_out;

    int n = in_sizes[0] / 2;            // N timesteps (x is [N,2])
    if (n > N_MAX) n = N_MAX;

    const int TPB = 128;
    int blocks = (n + TPB - 1) / TPB;
    phase1_kernel<<<blocks, TPB>>>(x, W_mz1, b_mz1, W_mz2, b_mz2,
                                   W_in1, b_in1, W_in2, b_in2,
                                   W_ih, b_ih, b_hh, n);
    phase2_kernel<<<1, 32>>>(W_hh, out, n);
}